// round 8
// baseline (speedup 1.0000x reference)
#include <cuda_runtime.h>
#include <cuda_fp16.h>
#include <cstdint>

// CGC layer — fp16 mma.sync m16n8k16 + ldmatrix operand loads.
// Inputs: x(8192,1024) Ws(4,1024,1024) bs(4,1024) Wt(3,4,1024,1024) bt(3,4,1024) Wg(3,1024,8)
// Output: mixture (3, 8192, 1024) f32

#define BATCH 8192
#define DM    1024
#define HD    1024
#define NTASK 3

__device__ float  g_y_buf[16ull * BATCH * HD];     // 512 MB expert outputs
__device__ float  g_gates[NTASK * BATCH * 8];
__device__ __half g_xh[(size_t)BATCH * DM];        // 16 MB x fp16 [b][k]
__device__ __half g_wh[16ull * DM * HD];           // 32 MB W fp16 transposed [e][n][k]

// ---------------------------------------------------------------------------
// helpers
// ---------------------------------------------------------------------------
__device__ __forceinline__ uint32_t smem_u32(const void* p) {
    uint32_t a;
    asm("{ .reg .u64 t; cvta.to.shared.u64 t, %1; cvt.u32.u64 %0, t; }" : "=r"(a) : "l"(p));
    return a;
}
__device__ __forceinline__ void cp_async16(uint32_t dst, const void* src) {
    asm volatile("cp.async.cg.shared.global [%0], [%1], 16;\n" :: "r"(dst), "l"(src) : "memory");
}
__device__ __forceinline__ void cp_commit() {
    asm volatile("cp.async.commit_group;\n" ::: "memory");
}
template <int N>
__device__ __forceinline__ void cp_wait_group() {
    asm volatile("cp.async.wait_group %0;\n" :: "n"(N) : "memory");
}
__device__ __forceinline__ void mma_f16(float* c, const uint32_t* a, const uint32_t* b) {
    asm volatile(
        "mma.sync.aligned.m16n8k16.row.col.f32.f16.f16.f32 "
        "{%0,%1,%2,%3}, {%4,%5,%6,%7}, {%8,%9}, {%0,%1,%2,%3};"
        : "+f"(c[0]), "+f"(c[1]), "+f"(c[2]), "+f"(c[3])
        : "r"(a[0]), "r"(a[1]), "r"(a[2]), "r"(a[3]), "r"(b[0]), "r"(b[1]));
}
__device__ __forceinline__ void ldsm_x4(uint32_t* r, uint32_t addr) {
    asm volatile("ldmatrix.sync.aligned.m8n8.x4.shared.b16 {%0,%1,%2,%3}, [%4];"
        : "=r"(r[0]), "=r"(r[1]), "=r"(r[2]), "=r"(r[3]) : "r"(addr));
}

// ---------------------------------------------------------------------------
// K0a: x fp32 -> fp16
// ---------------------------------------------------------------------------
__global__ __launch_bounds__(256) void cvt_x(const float* __restrict__ src,
                                             __half* __restrict__ dst)
{
    const size_t i = ((size_t)blockIdx.x * blockDim.x + threadIdx.x) * 8;
    float4 v0 = *(const float4*)(src + i);
    float4 v1 = *(const float4*)(src + i + 4);
    __half2 h[4];
    h[0] = __floats2half2_rn(v0.x, v0.y);
    h[1] = __floats2half2_rn(v0.z, v0.w);
    h[2] = __floats2half2_rn(v1.x, v1.y);
    h[3] = __floats2half2_rn(v1.z, v1.w);
    *(uint4*)(dst + i) = *(uint4*)h;
}

// ---------------------------------------------------------------------------
// K0b: W fp32 [e][k][n] -> fp16 transposed [e][n][k]
// ---------------------------------------------------------------------------
__global__ __launch_bounds__(256) void cvt_w(const float* __restrict__ Ws,
                                             const float* __restrict__ Wt)
{
    __shared__ float t[32][33];
    const int e = blockIdx.z;
    const float* src = (e < 4) ? Ws + (size_t)e * DM * HD
                               : Wt + (size_t)(e - 4) * DM * HD;
    const int n0 = blockIdx.x * 32;
    const int k0 = blockIdx.y * 32;
    const int tx = threadIdx.x & 31;
    const int ty = threadIdx.x >> 5;

    #pragma unroll
    for (int i = 0; i < 32; i += 8)
        t[ty + i][tx] = src[(size_t)(k0 + ty + i) * HD + n0 + tx];
    __syncthreads();
    __half* dst = g_wh + (size_t)e * DM * HD;
    #pragma unroll
    for (int i = 0; i < 32; i += 8)
        dst[(size_t)(n0 + ty + i) * DM + k0 + tx] = __float2half_rn(t[tx][ty + i]);
}

// ---------------------------------------------------------------------------
// K1: gate logits + softmax
// ---------------------------------------------------------------------------
__global__ __launch_bounds__(96) void gate_kernel(const float* __restrict__ x,
                                                  const float* __restrict__ Wg)
{
    const int b    = blockIdx.x;
    const int tid  = threadIdx.x;
    const int t    = tid >> 5;
    const int lane = tid & 31;

    __shared__ float xs[DM];
    for (int i = tid; i < DM; i += 96) xs[i] = x[(size_t)b * DM + i];
    __syncthreads();

    const float* Wgt = Wg + (size_t)t * DM * 8;
    float acc[8] = {0.f, 0.f, 0.f, 0.f, 0.f, 0.f, 0.f, 0.f};

    for (int d = lane; d < DM; d += 32) {
        float xv = xs[d];
        float4 w0 = *(const float4*)(Wgt + (size_t)d * 8);
        float4 w1 = *(const float4*)(Wgt + (size_t)d * 8 + 4);
        acc[0] = fmaf(xv, w0.x, acc[0]);
        acc[1] = fmaf(xv, w0.y, acc[1]);
        acc[2] = fmaf(xv, w0.z, acc[2]);
        acc[3] = fmaf(xv, w0.w, acc[3]);
        acc[4] = fmaf(xv, w1.x, acc[4]);
        acc[5] = fmaf(xv, w1.y, acc[5]);
        acc[6] = fmaf(xv, w1.z, acc[6]);
        acc[7] = fmaf(xv, w1.w, acc[7]);
    }
    #pragma unroll
    for (int off = 16; off > 0; off >>= 1) {
        #pragma unroll
        for (int j = 0; j < 8; j++)
            acc[j] += __shfl_down_sync(0xffffffffu, acc[j], off);
    }
    if (lane == 0) {
        float m = acc[0];
        #pragma unroll
        for (int j = 1; j < 8; j++) m = fmaxf(m, acc[j]);
        float e[8], s = 0.f;
        #pragma unroll
        for (int j = 0; j < 8; j++) { e[j] = expf(acc[j] - m); s += e[j]; }
        float inv = 1.f / s;
        float* gp = g_gates + ((size_t)t * BATCH + b) * 8;
        #pragma unroll
        for (int j = 0; j < 8; j++) gp[j] = e[j] * inv;
    }
}

// ---------------------------------------------------------------------------
// K2: fp16 mma.sync expert GEMM with ldmatrix.
// CTA tile 256(M) x 128(N) x 32(K); 8 warps 4(m)x2(n) -> 64x64 warp tiles.
// A smem [256][40] fp16 (80B rows), B smem [128][40] fp16 ([n][k]).
// 4-stage cp.async pipeline (123 KB).
// ---------------------------------------------------------------------------
#define STAGES      4
#define A_STRIDE_H  40
#define B_STRIDE_H  40
#define A_BYTES_H   (256 * A_STRIDE_H * 2)   // 20480
#define B_BYTES_H   (128 * B_STRIDE_H * 2)   // 10240
#define STAGE_H     (A_BYTES_H + B_BYTES_H)  // 30720
#define SMEM_GEMM   (STAGES * STAGE_H + 512)

__global__ __launch_bounds__(256, 1) void expert_gemm_f16(const float* __restrict__ bs,
                                                          const float* __restrict__ bt)
{
    extern __shared__ char smem[];
    const uint32_t sbase = smem_u32(smem);
    float* biassm = (float*)(smem + STAGES * STAGE_H);

    const int tid  = threadIdx.x;
    const int w    = tid >> 5;
    const int lane = tid & 31;
    const int gid  = lane >> 2;
    const int tig  = lane & 3;
    const int warp_m = (w >> 1) * 64;   // 0,64,128,192
    const int warp_n = (w & 1) * 64;    // 0,64

    const int e  = blockIdx.z;
    const int n0 = blockIdx.x * 128;
    const int m0 = blockIdx.y * 256;

    const __half* W   = g_wh + (size_t)e * DM * HD;      // [n][k]
    const float* bias = (e < 4) ? bs + (size_t)e * HD : bt + (size_t)(e - 4) * HD;
    float* Y = g_y_buf + (size_t)e * BATCH * HD;

    if (tid < 128) biassm[tid] = bias[n0 + tid];

    // ldmatrix lane-address bases (byte offsets within a stage)
    const uint32_t a_lane_off =
        (uint32_t)((warp_m + (lane & 7) + ((lane >> 3) & 1) * 8) * A_STRIDE_H
                   + (lane >> 4) * 8) * 2;
    const uint32_t b_lane_off =
        (uint32_t)(A_BYTES_H) +
        (uint32_t)((warp_n + (lane & 7) + (lane >> 4) * 8) * B_STRIDE_H
                   + ((lane >> 3) & 1) * 8) * 2;

    float c[4][8][4];
    #pragma unroll
    for (int mi = 0; mi < 4; mi++)
        #pragma unroll
        for (int ni = 0; ni < 8; ni++)
            #pragma unroll
            for (int r = 0; r < 4; r++) c[mi][ni][r] = 0.f;

    auto load_stage = [&](int s, int kt) {
        const uint32_t ab = sbase + (uint32_t)s * STAGE_H;
        const uint32_t bb = ab + A_BYTES_H;
        const int kbase = kt * 32;
        #pragma unroll
        for (int i = 0; i < 4; i++) {               // A: 1024 16B chunks
            const int idx = tid + i * 256;
            const int row = idx >> 2, q = idx & 3;
            cp_async16(ab + (uint32_t)(row * 80 + q * 16),
                       g_xh + (size_t)(m0 + row) * DM + kbase + q * 8);
        }
        #pragma unroll
        for (int i = 0; i < 2; i++) {               // B: 512 chunks
            const int idx = tid + i * 256;
            const int row = idx >> 2, q = idx & 3;
            cp_async16(bb + (uint32_t)(row * 80 + q * 16),
                       W + (size_t)(n0 + row) * DM + kbase + q * 8);
        }
        cp_commit();
    };

    load_stage(0, 0);
    load_stage(1, 1);
    load_stage(2, 2);

    for (int kt = 0; kt < 32; kt++) {
        __syncthreads();
        if (kt + 3 < 32) { load_stage((kt + 3) % STAGES, kt + 3); cp_wait_group<3>(); }
        else             { cp_wait_group<0>(); }
        __syncthreads();

        const uint32_t stage = sbase + (uint32_t)(kt % STAGES) * STAGE_H;
        const uint32_t a_base = stage + a_lane_off;
        const uint32_t b_base = stage + b_lane_off;

        #pragma unroll
        for (int ks = 0; ks < 2; ks++) {
            const uint32_t koff = (uint32_t)(ks * 16) * 2;   // 16 halves = 32 B
            uint32_t a[4][4];
            #pragma unroll
            for (int mi = 0; mi < 4; mi++)
                ldsm_x4(a[mi], a_base + (uint32_t)(mi * 16 * A_STRIDE_H) * 2 + koff);
            uint32_t b[8][2];
            #pragma unroll
            for (int np = 0; np < 4; np++) {
                uint32_t r[4];
                ldsm_x4(r, b_base + (uint32_t)(np * 16 * B_STRIDE_H) * 2 + koff);
                b[np * 2][0]     = r[0];
                b[np * 2][1]     = r[1];
                b[np * 2 + 1][0] = r[2];
                b[np * 2 + 1][1] = r[3];
            }
            #pragma unroll
            for (int mi = 0; mi < 4; mi++)
                #pragma unroll
                for (int ni = 0; ni < 8; ni++)
                    mma_f16(c[mi][ni], a[mi], b[ni]);
        }
    }

    // epilogue: bias + relu, float2 stores
    #pragma unroll
    for (int mi = 0; mi < 4; mi++) {
        #pragma unroll
        for (int ni = 0; ni < 8; ni++) {
            const int rbase = m0 + warp_m + mi * 16 + gid;
            const int col   = warp_n + ni * 8 + 2 * tig;
            const float b0 = biassm[col], b1 = biassm[col + 1];
            float2 v0, v1;
            v0.x = fmaxf(c[mi][ni][0] + b0, 0.f);
            v0.y = fmaxf(c[mi][ni][1] + b1, 0.f);
            v1.x = fmaxf(c[mi][ni][2] + b0, 0.f);
            v1.y = fmaxf(c[mi][ni][3] + b1, 0.f);
            *(float2*)(Y + (size_t)rbase * HD + n0 + col)       = v0;
            *(float2*)(Y + (size_t)(rbase + 8) * HD + n0 + col) = v1;
        }
    }
}

// ---------------------------------------------------------------------------
// K3: gated mixture
// ---------------------------------------------------------------------------
__global__ __launch_bounds__(256) void mix_kernel(float* __restrict__ out)
{
    const size_t idx = (size_t)blockIdx.x * blockDim.x + threadIdx.x;
    const int h4 = (int)(idx & 255);
    const size_t tb = idx >> 8;
    const int b = (int)(tb % BATCH);
    const int t = (int)(tb / BATCH);

    const float* gp = g_gates + ((size_t)t * BATCH + b) * 8;
    float g[8];
    #pragma unroll
    for (int j = 0; j < 8; j++) g[j] = gp[j];

    float4 acc = make_float4(0.f, 0.f, 0.f, 0.f);
    #pragma unroll
    for (int j = 0; j < 8; j++) {
        const int ei = (j < 4) ? (4 + t * 4 + j) : (j - 4);
        const float4 v = *(const float4*)(g_y_buf + ((size_t)ei * BATCH + b) * HD + (size_t)h4 * 4);
        acc.x = fmaf(g[j], v.x, acc.x);
        acc.y = fmaf(g[j], v.y, acc.y);
        acc.z = fmaf(g[j], v.z, acc.z);
        acc.w = fmaf(g[j], v.w, acc.w);
    }
    *(float4*)(out + idx * 4) = acc;
}

// ---------------------------------------------------------------------------
extern "C" void kernel_launch(void* const* d_in, const int* in_sizes, int n_in,
                              void* d_out, int out_size)
{
    (void)in_sizes; (void)n_in; (void)out_size;
    const float* x  = (const float*)d_in[0];
    const float* Ws = (const float*)d_in[1];
    const float* bs = (const float*)d_in[2];
    const float* Wt = (const float*)d_in[3];
    const float* bt = (const float*)d_in[4];
    const float* Wg = (const float*)d_in[5];
    float* out = (float*)d_out;

    cudaFuncSetAttribute(expert_gemm_f16,
                         cudaFuncAttributeMaxDynamicSharedMemorySize, SMEM_GEMM);

    {
        __half* xh = nullptr;
        cudaGetSymbolAddress((void**)&xh, g_xh);
        cvt_x<<<(unsigned)((size_t)BATCH * DM / 8 / 256), 256>>>(x, xh);
        cvt_w<<<dim3(32, 32, 16), 256>>>(Ws, Wt);
    }

    gate_kernel<<<BATCH, 96>>>(x, Wg);
    expert_gemm_f16<<<dim3(8, 32, 16), 256, SMEM_GEMM>>>(bs, bt);

    const size_t total4 = (size_t)NTASK * BATCH * (HD / 4);
    mix_kernel<<<(unsigned)(total4 / 256), 256>>>(out);
}

// round 9
// speedup vs baseline: 1.0317x; 1.0317x over previous
#include <cuda_runtime.h>
#include <cuda_fp16.h>
#include <cstdint>

// CGC layer — fp16 mma.sync m16n8k16 + ldmatrix, 16-warp CTA (4 warps/SMSP),
// fp16 expert-output buffer.
// Inputs: x(8192,1024) Ws(4,1024,1024) bs(4,1024) Wt(3,4,1024,1024) bt(3,4,1024) Wg(3,1024,8)
// Output: mixture (3, 8192, 1024) f32

#define BATCH 8192
#define DM    1024
#define HD    1024
#define NTASK 3

__device__ __half g_yh[16ull * BATCH * HD];        // 256 MB expert outputs (fp16)
__device__ float  g_gates[NTASK * BATCH * 8];
__device__ __half g_xh[(size_t)BATCH * DM];        // 16 MB x fp16 [b][k]
__device__ __half g_wh[16ull * DM * HD];           // 32 MB W fp16 transposed [e][n][k]

// ---------------------------------------------------------------------------
// helpers
// ---------------------------------------------------------------------------
__device__ __forceinline__ uint32_t smem_u32(const void* p) {
    uint32_t a;
    asm("{ .reg .u64 t; cvta.to.shared.u64 t, %1; cvt.u32.u64 %0, t; }" : "=r"(a) : "l"(p));
    return a;
}
__device__ __forceinline__ void cp_async16(uint32_t dst, const void* src) {
    asm volatile("cp.async.cg.shared.global [%0], [%1], 16;\n" :: "r"(dst), "l"(src) : "memory");
}
__device__ __forceinline__ void cp_commit() {
    asm volatile("cp.async.commit_group;\n" ::: "memory");
}
template <int N>
__device__ __forceinline__ void cp_wait_group() {
    asm volatile("cp.async.wait_group %0;\n" :: "n"(N) : "memory");
}
__device__ __forceinline__ void mma_f16(float* c, const uint32_t* a, const uint32_t* b) {
    asm volatile(
        "mma.sync.aligned.m16n8k16.row.col.f32.f16.f16.f32 "
        "{%0,%1,%2,%3}, {%4,%5,%6,%7}, {%8,%9}, {%0,%1,%2,%3};"
        : "+f"(c[0]), "+f"(c[1]), "+f"(c[2]), "+f"(c[3])
        : "r"(a[0]), "r"(a[1]), "r"(a[2]), "r"(a[3]), "r"(b[0]), "r"(b[1]));
}
__device__ __forceinline__ void ldsm_x4(uint32_t* r, uint32_t addr) {
    asm volatile("ldmatrix.sync.aligned.m8n8.x4.shared.b16 {%0,%1,%2,%3}, [%4];"
        : "=r"(r[0]), "=r"(r[1]), "=r"(r[2]), "=r"(r[3]) : "r"(addr));
}

// ---------------------------------------------------------------------------
// K0a: x fp32 -> fp16
// ---------------------------------------------------------------------------
__global__ __launch_bounds__(256) void cvt_x(const float* __restrict__ src,
                                             __half* __restrict__ dst)
{
    const size_t i = ((size_t)blockIdx.x * blockDim.x + threadIdx.x) * 8;
    float4 v0 = *(const float4*)(src + i);
    float4 v1 = *(const float4*)(src + i + 4);
    __half2 h[4];
    h[0] = __floats2half2_rn(v0.x, v0.y);
    h[1] = __floats2half2_rn(v0.z, v0.w);
    h[2] = __floats2half2_rn(v1.x, v1.y);
    h[3] = __floats2half2_rn(v1.z, v1.w);
    *(uint4*)(dst + i) = *(uint4*)h;
}

// ---------------------------------------------------------------------------
// K0b: W fp32 [e][k][n] -> fp16 transposed [e][n][k]
// ---------------------------------------------------------------------------
__global__ __launch_bounds__(256) void cvt_w(const float* __restrict__ Ws,
                                             const float* __restrict__ Wt)
{
    __shared__ float t[32][33];
    const int e = blockIdx.z;
    const float* src = (e < 4) ? Ws + (size_t)e * DM * HD
                               : Wt + (size_t)(e - 4) * DM * HD;
    const int n0 = blockIdx.x * 32;
    const int k0 = blockIdx.y * 32;
    const int tx = threadIdx.x & 31;
    const int ty = threadIdx.x >> 5;

    #pragma unroll
    for (int i = 0; i < 32; i += 8)
        t[ty + i][tx] = src[(size_t)(k0 + ty + i) * HD + n0 + tx];
    __syncthreads();
    __half* dst = g_wh + (size_t)e * DM * HD;
    #pragma unroll
    for (int i = 0; i < 32; i += 8)
        dst[(size_t)(n0 + ty + i) * DM + k0 + tx] = __float2half_rn(t[tx][ty + i]);
}

// ---------------------------------------------------------------------------
// K1: gate logits + softmax
// ---------------------------------------------------------------------------
__global__ __launch_bounds__(96) void gate_kernel(const float* __restrict__ x,
                                                  const float* __restrict__ Wg)
{
    const int b    = blockIdx.x;
    const int tid  = threadIdx.x;
    const int t    = tid >> 5;
    const int lane = tid & 31;

    __shared__ float xs[DM];
    for (int i = tid; i < DM; i += 96) xs[i] = x[(size_t)b * DM + i];
    __syncthreads();

    const float* Wgt = Wg + (size_t)t * DM * 8;
    float acc[8] = {0.f, 0.f, 0.f, 0.f, 0.f, 0.f, 0.f, 0.f};

    for (int d = lane; d < DM; d += 32) {
        float xv = xs[d];
        float4 w0 = *(const float4*)(Wgt + (size_t)d * 8);
        float4 w1 = *(const float4*)(Wgt + (size_t)d * 8 + 4);
        acc[0] = fmaf(xv, w0.x, acc[0]);
        acc[1] = fmaf(xv, w0.y, acc[1]);
        acc[2] = fmaf(xv, w0.z, acc[2]);
        acc[3] = fmaf(xv, w0.w, acc[3]);
        acc[4] = fmaf(xv, w1.x, acc[4]);
        acc[5] = fmaf(xv, w1.y, acc[5]);
        acc[6] = fmaf(xv, w1.z, acc[6]);
        acc[7] = fmaf(xv, w1.w, acc[7]);
    }
    #pragma unroll
    for (int off = 16; off > 0; off >>= 1) {
        #pragma unroll
        for (int j = 0; j < 8; j++)
            acc[j] += __shfl_down_sync(0xffffffffu, acc[j], off);
    }
    if (lane == 0) {
        float m = acc[0];
        #pragma unroll
        for (int j = 1; j < 8; j++) m = fmaxf(m, acc[j]);
        float e[8], s = 0.f;
        #pragma unroll
        for (int j = 0; j < 8; j++) { e[j] = expf(acc[j] - m); s += e[j]; }
        float inv = 1.f / s;
        float* gp = g_gates + ((size_t)t * BATCH + b) * 8;
        #pragma unroll
        for (int j = 0; j < 8; j++) gp[j] = e[j] * inv;
    }
}

// ---------------------------------------------------------------------------
// K2: fp16 mma.sync expert GEMM, 512 threads / 16 warps (4 per SMSP).
// CTA tile 256(M) x 128(N) x 32(K); warps 4(m)x4(n) -> 64x32 warp tiles.
// A smem [256][40] fp16, B smem [128][40] fp16 ([n][k]); 4-stage cp.async.
// ---------------------------------------------------------------------------
#define STAGES      4
#define A_STRIDE_H  40
#define B_STRIDE_H  40
#define A_BYTES_H   (256 * A_STRIDE_H * 2)   // 20480
#define B_BYTES_H   (128 * B_STRIDE_H * 2)   // 10240
#define STAGE_H     (A_BYTES_H + B_BYTES_H)  // 30720
#define SMEM_GEMM   (STAGES * STAGE_H + 512)

__global__ __launch_bounds__(512, 1) void expert_gemm_f16(const float* __restrict__ bs,
                                                          const float* __restrict__ bt)
{
    extern __shared__ char smem[];
    const uint32_t sbase = smem_u32(smem);
    float* biassm = (float*)(smem + STAGES * STAGE_H);

    const int tid  = threadIdx.x;
    const int w    = tid >> 5;
    const int lane = tid & 31;
    const int gid  = lane >> 2;
    const int tig  = lane & 3;
    const int warp_m = (w >> 2) * 64;   // 0,64,128,192
    const int warp_n = (w & 3) * 32;    // 0,32,64,96

    const int e  = blockIdx.z;
    const int n0 = blockIdx.x * 128;
    const int m0 = blockIdx.y * 256;

    const __half* W   = g_wh + (size_t)e * DM * HD;      // [n][k]
    const float* bias = (e < 4) ? bs + (size_t)e * HD : bt + (size_t)(e - 4) * HD;
    __half* Y = g_yh + (size_t)e * BATCH * HD;

    if (tid < 128) biassm[tid] = bias[n0 + tid];

    // ldmatrix lane-address bases (byte offsets within a stage)
    const uint32_t a_lane_off =
        (uint32_t)((warp_m + (lane & 7) + ((lane >> 3) & 1) * 8) * A_STRIDE_H
                   + (lane >> 4) * 8) * 2;
    const uint32_t b_lane_off =
        (uint32_t)(A_BYTES_H) +
        (uint32_t)((warp_n + (lane & 7) + (lane >> 4) * 8) * B_STRIDE_H
                   + ((lane >> 3) & 1) * 8) * 2;

    float c[4][4][4];
    #pragma unroll
    for (int mi = 0; mi < 4; mi++)
        #pragma unroll
        for (int ni = 0; ni < 4; ni++)
            #pragma unroll
            for (int r = 0; r < 4; r++) c[mi][ni][r] = 0.f;

    auto load_stage = [&](int s, int kt) {
        const uint32_t ab = sbase + (uint32_t)s * STAGE_H;
        const uint32_t bb = ab + A_BYTES_H;
        const int kbase = kt * 32;
        #pragma unroll
        for (int i = 0; i < 2; i++) {               // A: 1024 16B chunks
            const int idx = tid + i * 512;
            const int row = idx >> 2, q = idx & 3;
            cp_async16(ab + (uint32_t)(row * 80 + q * 16),
                       g_xh + (size_t)(m0 + row) * DM + kbase + q * 8);
        }
        {                                            // B: 512 chunks
            const int row = tid >> 2, q = tid & 3;
            cp_async16(bb + (uint32_t)(row * 80 + q * 16),
                       W + (size_t)(n0 + row) * DM + kbase + q * 8);
        }
        cp_commit();
    };

    load_stage(0, 0);
    load_stage(1, 1);
    load_stage(2, 2);

    for (int kt = 0; kt < 32; kt++) {
        __syncthreads();
        if (kt + 3 < 32) { load_stage((kt + 3) % STAGES, kt + 3); cp_wait_group<3>(); }
        else             { cp_wait_group<0>(); }
        __syncthreads();

        const uint32_t stage = sbase + (uint32_t)(kt % STAGES) * STAGE_H;
        const uint32_t a_base = stage + a_lane_off;
        const uint32_t b_base = stage + b_lane_off;

        #pragma unroll
        for (int ks = 0; ks < 2; ks++) {
            const uint32_t koff = (uint32_t)(ks * 16) * 2;   // 16 halves = 32 B
            uint32_t a[4][4];
            #pragma unroll
            for (int mi = 0; mi < 4; mi++)
                ldsm_x4(a[mi], a_base + (uint32_t)(mi * 16 * A_STRIDE_H) * 2 + koff);
            uint32_t b[4][2];
            {
                uint32_t r[4];
                ldsm_x4(r, b_base + koff);                              // n rows 0..15
                b[0][0] = r[0]; b[0][1] = r[1]; b[1][0] = r[2]; b[1][1] = r[3];
                ldsm_x4(r, b_base + (uint32_t)(16 * B_STRIDE_H) * 2 + koff);  // n rows 16..31
                b[2][0] = r[0]; b[2][1] = r[1]; b[3][0] = r[2]; b[3][1] = r[3];
            }
            #pragma unroll
            for (int mi = 0; mi < 4; mi++)
                #pragma unroll
                for (int ni = 0; ni < 4; ni++)
                    mma_f16(c[mi][ni], a[mi], b[ni]);
        }
    }

    // epilogue: bias + relu -> fp16 stores (half2 = 4B each)
    #pragma unroll
    for (int mi = 0; mi < 4; mi++) {
        #pragma unroll
        for (int ni = 0; ni < 4; ni++) {
            const int rbase = m0 + warp_m + mi * 16 + gid;
            const int col   = warp_n + ni * 8 + 2 * tig;
            const float b0 = biassm[col], b1 = biassm[col + 1];
            __half2 p0 = __floats2half2_rn(fmaxf(c[mi][ni][0] + b0, 0.f),
                                           fmaxf(c[mi][ni][1] + b1, 0.f));
            __half2 p1 = __floats2half2_rn(fmaxf(c[mi][ni][2] + b0, 0.f),
                                           fmaxf(c[mi][ni][3] + b1, 0.f));
            *(__half2*)(Y + (size_t)rbase * HD + n0 + col)       = p0;
            *(__half2*)(Y + (size_t)(rbase + 8) * HD + n0 + col) = p1;
        }
    }
}

// ---------------------------------------------------------------------------
// K3: gated mixture (reads fp16 y, writes fp32 out)
// ---------------------------------------------------------------------------
__global__ __launch_bounds__(256) void mix_kernel(float* __restrict__ out)
{
    const size_t idx = (size_t)blockIdx.x * blockDim.x + threadIdx.x;
    const int h4 = (int)(idx & 255);
    const size_t tb = idx >> 8;
    const int b = (int)(tb % BATCH);
    const int t = (int)(tb / BATCH);

    const float* gp = g_gates + ((size_t)t * BATCH + b) * 8;
    float g[8];
    #pragma unroll
    for (int j = 0; j < 8; j++) g[j] = gp[j];

    float4 acc = make_float4(0.f, 0.f, 0.f, 0.f);
    #pragma unroll
    for (int j = 0; j < 8; j++) {
        const int ei = (j < 4) ? (4 + t * 4 + j) : (j - 4);
        const uint2 v = *(const uint2*)(g_yh + ((size_t)ei * BATCH + b) * HD + (size_t)h4 * 4);
        const float2 f01 = __half22float2(*(const __half2*)&v.x);
        const float2 f23 = __half22float2(*(const __half2*)&v.y);
        acc.x = fmaf(g[j], f01.x, acc.x);
        acc.y = fmaf(g[j], f01.y, acc.y);
        acc.z = fmaf(g[j], f23.x, acc.z);
        acc.w = fmaf(g[j], f23.y, acc.w);
    }
    *(float4*)(out + idx * 4) = acc;
}

// ---------------------------------------------------------------------------
extern "C" void kernel_launch(void* const* d_in, const int* in_sizes, int n_in,
                              void* d_out, int out_size)
{
    (void)in_sizes; (void)n_in; (void)out_size;
    const float* x  = (const float*)d_in[0];
    const float* Ws = (const float*)d_in[1];
    const float* bs = (const float*)d_in[2];
    const float* Wt = (const float*)d_in[3];
    const float* bt = (const float*)d_in[4];
    const float* Wg = (const float*)d_in[5];
    float* out = (float*)d_out;

    cudaFuncSetAttribute(expert_gemm_f16,
                         cudaFuncAttributeMaxDynamicSharedMemorySize, SMEM_GEMM);

    {
        __half* xh = nullptr;
        cudaGetSymbolAddress((void**)&xh, g_xh);
        cvt_x<<<(unsigned)((size_t)BATCH * DM / 8 / 256), 256>>>(x, xh);
        cvt_w<<<dim3(32, 32, 16), 256>>>(Ws, Wt);
    }

    gate_kernel<<<BATCH, 96>>>(x, Wg);
    expert_gemm_f16<<<dim3(8, 32, 16), 512, SMEM_GEMM>>>(bs, bt);

    const size_t total4 = (size_t)NTASK * BATCH * (HD / 4);
    mix_kernel<<<(unsigned)(total4 / 256), 256>>>(out);
}

// round 10
// speedup vs baseline: 1.2237x; 1.1861x over previous
#include <cuda_runtime.h>
#include <cuda_fp16.h>
#include <cstdint>

// CGC layer — fp16 mma.sync m16n8k16 + ldmatrix; 128x128 CTA tile, 2 CTAs/SM,
// single-barrier multistage mainloop; smem-staged gate kernel.
// Inputs: x(8192,1024) Ws(4,1024,1024) bs(4,1024) Wt(3,4,1024,1024) bt(3,4,1024) Wg(3,1024,8)
// Output: mixture (3, 8192, 1024) f32

#define BATCH 8192
#define DM    1024
#define HD    1024
#define NTASK 3

__device__ __half g_yh[16ull * BATCH * HD];        // 256 MB expert outputs (fp16)
__device__ float  g_gates[NTASK * BATCH * 8];
__device__ __half g_xh[(size_t)BATCH * DM];        // 16 MB x fp16 [b][k]
__device__ __half g_wh[16ull * DM * HD];           // 32 MB W fp16 transposed [e][n][k]

// ---------------------------------------------------------------------------
// helpers
// ---------------------------------------------------------------------------
__device__ __forceinline__ uint32_t smem_u32(const void* p) {
    uint32_t a;
    asm("{ .reg .u64 t; cvta.to.shared.u64 t, %1; cvt.u32.u64 %0, t; }" : "=r"(a) : "l"(p));
    return a;
}
__device__ __forceinline__ void cp_async16(uint32_t dst, const void* src) {
    asm volatile("cp.async.cg.shared.global [%0], [%1], 16;\n" :: "r"(dst), "l"(src) : "memory");
}
__device__ __forceinline__ void cp_commit() {
    asm volatile("cp.async.commit_group;\n" ::: "memory");
}
template <int N>
__device__ __forceinline__ void cp_wait_group() {
    asm volatile("cp.async.wait_group %0;\n" :: "n"(N) : "memory");
}
__device__ __forceinline__ void mma_f16(float* c, const uint32_t* a, const uint32_t* b) {
    asm volatile(
        "mma.sync.aligned.m16n8k16.row.col.f32.f16.f16.f32 "
        "{%0,%1,%2,%3}, {%4,%5,%6,%7}, {%8,%9}, {%0,%1,%2,%3};"
        : "+f"(c[0]), "+f"(c[1]), "+f"(c[2]), "+f"(c[3])
        : "r"(a[0]), "r"(a[1]), "r"(a[2]), "r"(a[3]), "r"(b[0]), "r"(b[1]));
}
__device__ __forceinline__ void ldsm_x4(uint32_t* r, uint32_t addr) {
    asm volatile("ldmatrix.sync.aligned.m8n8.x4.shared.b16 {%0,%1,%2,%3}, [%4];"
        : "=r"(r[0]), "=r"(r[1]), "=r"(r[2]), "=r"(r[3]) : "r"(addr));
}

// ---------------------------------------------------------------------------
// K0a: x fp32 -> fp16
// ---------------------------------------------------------------------------
__global__ __launch_bounds__(256) void cvt_x(const float* __restrict__ src,
                                             __half* __restrict__ dst)
{
    const size_t i = ((size_t)blockIdx.x * blockDim.x + threadIdx.x) * 8;
    float4 v0 = *(const float4*)(src + i);
    float4 v1 = *(const float4*)(src + i + 4);
    __half2 h[4];
    h[0] = __floats2half2_rn(v0.x, v0.y);
    h[1] = __floats2half2_rn(v0.z, v0.w);
    h[2] = __floats2half2_rn(v1.x, v1.y);
    h[3] = __floats2half2_rn(v1.z, v1.w);
    *(uint4*)(dst + i) = *(uint4*)h;
}

// ---------------------------------------------------------------------------
// K0b: W fp32 [e][k][n] -> fp16 transposed [e][n][k]
// ---------------------------------------------------------------------------
__global__ __launch_bounds__(256) void cvt_w(const float* __restrict__ Ws,
                                             const float* __restrict__ Wt)
{
    __shared__ float t[32][33];
    const int e = blockIdx.z;
    const float* src = (e < 4) ? Ws + (size_t)e * DM * HD
                               : Wt + (size_t)(e - 4) * DM * HD;
    const int n0 = blockIdx.x * 32;
    const int k0 = blockIdx.y * 32;
    const int tx = threadIdx.x & 31;
    const int ty = threadIdx.x >> 5;

    #pragma unroll
    for (int i = 0; i < 32; i += 8)
        t[ty + i][tx] = src[(size_t)(k0 + ty + i) * HD + n0 + tx];
    __syncthreads();
    __half* dst = g_wh + (size_t)e * DM * HD;
    #pragma unroll
    for (int i = 0; i < 32; i += 8)
        dst[(size_t)(n0 + ty + i) * DM + k0 + tx] = __float2half_rn(t[tx][ty + i]);
}

// ---------------------------------------------------------------------------
// K1: gate logits + softmax. 256 blocks x 32 rows; Wg staged in smem once.
// ---------------------------------------------------------------------------
#define GATE_ROWS 32
#define GATE_SMEM (NTASK * DM * 8 * 4)   // 98304 bytes

__global__ __launch_bounds__(256) void gate_kernel(const float* __restrict__ x,
                                                   const float* __restrict__ Wg)
{
    extern __shared__ float wgs[];       // [3][1024][8]
    const int tid = threadIdx.x;

    for (int i = tid; i < NTASK * DM * 8 / 4; i += 256)
        ((float4*)wgs)[i] = ((const float4*)Wg)[i];
    __syncthreads();

    const int w    = tid >> 5;
    const int lane = tid & 31;
    const int b0   = blockIdx.x * GATE_ROWS;

    for (int i = w; i < GATE_ROWS * NTASK; i += 8) {
        const int row = i & 31;
        const int t   = i >> 5;
        const float* xr = x + (size_t)(b0 + row) * DM;
        const float* wt = wgs + (size_t)t * DM * 8;

        float acc[8] = {0.f, 0.f, 0.f, 0.f, 0.f, 0.f, 0.f, 0.f};
        for (int d = lane; d < DM; d += 32) {
            const float xv = xr[d];
            float4 w0 = *(const float4*)(wt + (size_t)d * 8);
            float4 w1 = *(const float4*)(wt + (size_t)d * 8 + 4);
            acc[0] = fmaf(xv, w0.x, acc[0]);
            acc[1] = fmaf(xv, w0.y, acc[1]);
            acc[2] = fmaf(xv, w0.z, acc[2]);
            acc[3] = fmaf(xv, w0.w, acc[3]);
            acc[4] = fmaf(xv, w1.x, acc[4]);
            acc[5] = fmaf(xv, w1.y, acc[5]);
            acc[6] = fmaf(xv, w1.z, acc[6]);
            acc[7] = fmaf(xv, w1.w, acc[7]);
        }
        #pragma unroll
        for (int off = 16; off > 0; off >>= 1) {
            #pragma unroll
            for (int j = 0; j < 8; j++)
                acc[j] += __shfl_down_sync(0xffffffffu, acc[j], off);
        }
        if (lane == 0) {
            float m = acc[0];
            #pragma unroll
            for (int j = 1; j < 8; j++) m = fmaxf(m, acc[j]);
            float e[8], s = 0.f;
            #pragma unroll
            for (int j = 0; j < 8; j++) { e[j] = expf(acc[j] - m); s += e[j]; }
            float inv = 1.f / s;
            float* gp = g_gates + ((size_t)t * BATCH + (b0 + row)) * 8;
            #pragma unroll
            for (int j = 0; j < 8; j++) gp[j] = e[j] * inv;
        }
    }
}

// ---------------------------------------------------------------------------
// K2: fp16 mma.sync expert GEMM, 128x128x32 CTA tile, 8 warps (2m x 4n),
// 64x32 warp tiles, 4-stage cp.async, ONE barrier per k-tile, 2 CTAs/SM.
// A smem [128][40] fp16, B smem [128][40] fp16 ([n][k]).
// ---------------------------------------------------------------------------
#define STAGES      4
#define A_STRIDE_H  40
#define B_STRIDE_H  40
#define A_BYTES_H   (128 * A_STRIDE_H * 2)   // 10240
#define B_BYTES_H   (128 * B_STRIDE_H * 2)   // 10240
#define STAGE_H     (A_BYTES_H + B_BYTES_H)  // 20480
#define SMEM_GEMM   (STAGES * STAGE_H + 512) // 82432

__global__ __launch_bounds__(256, 2) void expert_gemm_f16(const float* __restrict__ bs,
                                                          const float* __restrict__ bt)
{
    extern __shared__ char smem[];
    const uint32_t sbase = smem_u32(smem);
    float* biassm = (float*)(smem + STAGES * STAGE_H);

    const int tid  = threadIdx.x;
    const int w    = tid >> 5;
    const int lane = tid & 31;
    const int gid  = lane >> 2;
    const int tig  = lane & 3;
    const int warp_m = (w >> 2) * 64;   // 0,64
    const int warp_n = (w & 3) * 32;    // 0,32,64,96

    const int e  = blockIdx.z;
    const int n0 = blockIdx.x * 128;
    const int m0 = blockIdx.y * 128;

    const __half* W   = g_wh + (size_t)e * DM * HD;      // [n][k]
    const float* bias = (e < 4) ? bs + (size_t)e * HD : bt + (size_t)(e - 4) * HD;
    __half* Y = g_yh + (size_t)e * BATCH * HD;

    if (tid < 128) biassm[tid] = bias[n0 + tid];

    // ldmatrix lane-address bases (byte offsets within a stage)
    const uint32_t a_lane_off =
        (uint32_t)((warp_m + (lane & 7) + ((lane >> 3) & 1) * 8) * A_STRIDE_H
                   + (lane >> 4) * 8) * 2;
    const uint32_t b_lane_off =
        (uint32_t)(A_BYTES_H) +
        (uint32_t)((warp_n + (lane & 7) + (lane >> 4) * 8) * B_STRIDE_H
                   + ((lane >> 3) & 1) * 8) * 2;

    float c[4][4][4];
    #pragma unroll
    for (int mi = 0; mi < 4; mi++)
        #pragma unroll
        for (int ni = 0; ni < 4; ni++)
            #pragma unroll
            for (int r = 0; r < 4; r++) c[mi][ni][r] = 0.f;

    // stage loader: A 128x32 fp16 (512 chunks), B 128x32 fp16 (512 chunks)
    auto load_stage = [&](int s, int kt) {
        const uint32_t ab = sbase + (uint32_t)s * STAGE_H;
        const uint32_t bb = ab + A_BYTES_H;
        const int kbase = kt * 32;
        #pragma unroll
        for (int i = 0; i < 2; i++) {
            const int idx = tid + i * 256;
            const int row = idx >> 2, q = idx & 3;
            cp_async16(ab + (uint32_t)(row * 80 + q * 16),
                       g_xh + (size_t)(m0 + row) * DM + kbase + q * 8);
        }
        #pragma unroll
        for (int i = 0; i < 2; i++) {
            const int idx = tid + i * 256;
            const int row = idx >> 2, q = idx & 3;
            cp_async16(bb + (uint32_t)(row * 80 + q * 16),
                       W + (size_t)(n0 + row) * DM + kbase + q * 8);
        }
        cp_commit();
    };

    load_stage(0, 0);
    load_stage(1, 1);
    load_stage(2, 2);

    for (int kt = 0; kt < 32; kt++) {
        // ensure group kt complete (tail: fewer groups outstanding)
        if (kt < 30)      cp_wait_group<2>();
        else if (kt == 30) cp_wait_group<1>();
        else               cp_wait_group<0>();
        __syncthreads();   // stage kt visible to all; nobody reads stage kt-1 anymore

        if (kt + 3 < 32) load_stage((kt + 3) % STAGES, kt + 3);  // overwrites (kt-1)%4

        const uint32_t stage = sbase + (uint32_t)(kt % STAGES) * STAGE_H;
        const uint32_t a_base = stage + a_lane_off;
        const uint32_t b_base = stage + b_lane_off;

        #pragma unroll
        for (int ks = 0; ks < 2; ks++) {
            const uint32_t koff = (uint32_t)(ks * 16) * 2;   // 32 B
            uint32_t a[4][4];
            #pragma unroll
            for (int mi = 0; mi < 4; mi++)
                ldsm_x4(a[mi], a_base + (uint32_t)(mi * 16 * A_STRIDE_H) * 2 + koff);
            uint32_t b[4][2];
            {
                uint32_t r[4];
                ldsm_x4(r, b_base + koff);                                   // n 0..15
                b[0][0] = r[0]; b[0][1] = r[1]; b[1][0] = r[2]; b[1][1] = r[3];
                ldsm_x4(r, b_base + (uint32_t)(16 * B_STRIDE_H) * 2 + koff); // n 16..31
                b[2][0] = r[0]; b[2][1] = r[1]; b[3][0] = r[2]; b[3][1] = r[3];
            }
            #pragma unroll
            for (int mi = 0; mi < 4; mi++)
                #pragma unroll
                for (int ni = 0; ni < 4; ni++)
                    mma_f16(c[mi][ni], a[mi], b[ni]);
        }
    }

    // epilogue: bias + relu -> fp16 stores
    #pragma unroll
    for (int mi = 0; mi < 4; mi++) {
        #pragma unroll
        for (int ni = 0; ni < 4; ni++) {
            const int rbase = m0 + warp_m + mi * 16 + gid;
            const int col   = warp_n + ni * 8 + 2 * tig;
            const float b0 = biassm[col], b1 = biassm[col + 1];
            __half2 p0 = __floats2half2_rn(fmaxf(c[mi][ni][0] + b0, 0.f),
                                           fmaxf(c[mi][ni][1] + b1, 0.f));
            __half2 p1 = __floats2half2_rn(fmaxf(c[mi][ni][2] + b0, 0.f),
                                           fmaxf(c[mi][ni][3] + b1, 0.f));
            *(__half2*)(Y + (size_t)rbase * HD + n0 + col)       = p0;
            *(__half2*)(Y + (size_t)(rbase + 8) * HD + n0 + col) = p1;
        }
    }
}

// ---------------------------------------------------------------------------
// K3: gated mixture (reads fp16 y, writes fp32 out)
// ---------------------------------------------------------------------------
__global__ __launch_bounds__(256) void mix_kernel(float* __restrict__ out)
{
    const size_t idx = (size_t)blockIdx.x * blockDim.x + threadIdx.x;
    const int h4 = (int)(idx & 255);
    const size_t tb = idx >> 8;
    const int b = (int)(tb % BATCH);
    const int t = (int)(tb / BATCH);

    const float* gp = g_gates + ((size_t)t * BATCH + b) * 8;
    float g[8];
    #pragma unroll
    for (int j = 0; j < 8; j++) g[j] = gp[j];

    float4 acc = make_float4(0.f, 0.f, 0.f, 0.f);
    #pragma unroll
    for (int j = 0; j < 8; j++) {
        const int ei = (j < 4) ? (4 + t * 4 + j) : (j - 4);
        const uint2 v = *(const uint2*)(g_yh + ((size_t)ei * BATCH + b) * HD + (size_t)h4 * 4);
        const float2 f01 = __half22float2(*(const __half2*)&v.x);
        const float2 f23 = __half22float2(*(const __half2*)&v.y);
        acc.x = fmaf(g[j], f01.x, acc.x);
        acc.y = fmaf(g[j], f01.y, acc.y);
        acc.z = fmaf(g[j], f23.x, acc.z);
        acc.w = fmaf(g[j], f23.y, acc.w);
    }
    *(float4*)(out + idx * 4) = acc;
}

// ---------------------------------------------------------------------------
extern "C" void kernel_launch(void* const* d_in, const int* in_sizes, int n_in,
                              void* d_out, int out_size)
{
    (void)in_sizes; (void)n_in; (void)out_size;
    const float* x  = (const float*)d_in[0];
    const float* Ws = (const float*)d_in[1];
    const float* bs = (const float*)d_in[2];
    const float* Wt = (const float*)d_in[3];
    const float* bt = (const float*)d_in[4];
    const float* Wg = (const float*)d_in[5];
    float* out = (float*)d_out;

    cudaFuncSetAttribute(expert_gemm_f16,
                         cudaFuncAttributeMaxDynamicSharedMemorySize, SMEM_GEMM);
    cudaFuncSetAttribute(gate_kernel,
                         cudaFuncAttributeMaxDynamicSharedMemorySize, GATE_SMEM);

    {
        __half* xh = nullptr;
        cudaGetSymbolAddress((void**)&xh, g_xh);
        cvt_x<<<(unsigned)((size_t)BATCH * DM / 8 / 256), 256>>>(x, xh);
        cvt_w<<<dim3(32, 32, 16), 256>>>(Ws, Wt);
    }

    gate_kernel<<<BATCH / GATE_ROWS, 256, GATE_SMEM>>>(x, Wg);
    expert_gemm_f16<<<dim3(8, 64, 16), 256, SMEM_GEMM>>>(bs, bt);

    const size_t total4 = (size_t)NTASK * BATCH * (HD / 4);
    mix_kernel<<<(unsigned)(total4 / 256), 256>>>(out);
}